// round 1
// baseline (speedup 1.0000x reference)
#include <cuda_runtime.h>
#include <math.h>

// RoutingLayer: out[B,64] = scatter(softmax(top2(x@w_gate + noise*(softplus(x@w_noise)+0.01))))
// B=32768, D=2048, E=64.
//
// Fused as one GEMM: C[128 rows x 128 cols] per block, cols 0..63 = gate logits,
// cols 64..127 = noise logits. Epilogue done in registers + half-warp shuffles.

#define BM 128
#define BN 128
#define BK 16
#define TM 8
#define TN 8   // 4 gate cols + 4 noise cols
#define KDIM 2048
#define EDIM 64

__global__ __launch_bounds__(256, 2)
void routing_kernel(const float* __restrict__ x,
                    const float* __restrict__ wg,
                    const float* __restrict__ wn,
                    const float* __restrict__ nz,
                    float* __restrict__ out)
{
    // a_s: transposed x tile [k][row], padded to 132 (16B-aligned rows, reduced write conflicts)
    __shared__ float a_s[2][BK][BM + 4];
    __shared__ float b_s[2][BK][BN];

    const int tid = threadIdx.x;
    const int tx = tid & 15;    // col group 0..15
    const int ty = tid >> 4;    // row group 0..15
    const int r0 = blockIdx.x * BM;

    // x global-load mapping: thread covers (row=tid/4, kq=(tid%4)*4) and row+64
    const int lrow = tid >> 2;          // 0..63
    const int lkq  = (tid & 3) << 2;    // 0,4,8,12
    // w load mapping: k = ty (0..15), n4 = tx*4 (0..60)

    float acc[TM][TN];
    #pragma unroll
    for (int i = 0; i < TM; i++)
        #pragma unroll
        for (int j = 0; j < TN; j++) acc[i][j] = 0.f;

    const int NT = KDIM / BK;   // 128

    float4 xa, xb, wga, wna;

    // prologue: load tile 0
    {
        const int k0 = 0;
        xa  = *(const float4*)(x + (size_t)(r0 + lrow) * KDIM + k0 + lkq);
        xb  = *(const float4*)(x + (size_t)(r0 + 64 + lrow) * KDIM + k0 + lkq);
        wga = *(const float4*)(wg + (size_t)(k0 + ty) * EDIM + tx * 4);
        wna = *(const float4*)(wn + (size_t)(k0 + ty) * EDIM + tx * 4);
    }
    // store tile 0 into buffer 0
    {
        a_s[0][lkq + 0][lrow] = xa.x;
        a_s[0][lkq + 1][lrow] = xa.y;
        a_s[0][lkq + 2][lrow] = xa.z;
        a_s[0][lkq + 3][lrow] = xa.w;
        a_s[0][lkq + 0][lrow + 64] = xb.x;
        a_s[0][lkq + 1][lrow + 64] = xb.y;
        a_s[0][lkq + 2][lrow + 64] = xb.z;
        a_s[0][lkq + 3][lrow + 64] = xb.w;
        *(float4*)&b_s[0][ty][tx * 4]      = wga;
        *(float4*)&b_s[0][ty][64 + tx * 4] = wna;
    }
    __syncthreads();

    int p = 0;
    for (int t = 0; t < NT; t++) {
        // prefetch next tile into registers
        if (t + 1 < NT) {
            const int k0 = (t + 1) * BK;
            xa  = *(const float4*)(x + (size_t)(r0 + lrow) * KDIM + k0 + lkq);
            xb  = *(const float4*)(x + (size_t)(r0 + 64 + lrow) * KDIM + k0 + lkq);
            wga = *(const float4*)(wg + (size_t)(k0 + ty) * EDIM + tx * 4);
            wna = *(const float4*)(wn + (size_t)(k0 + ty) * EDIM + tx * 4);
        }

        // compute on buffer p
        #pragma unroll
        for (int k = 0; k < BK; k++) {
            float af[TM], bf[TN];
            *(float4*)&af[0] = *(const float4*)&a_s[p][k][ty * 8];
            *(float4*)&af[4] = *(const float4*)&a_s[p][k][ty * 8 + 4];
            *(float4*)&bf[0] = *(const float4*)&b_s[p][k][tx * 4];
            *(float4*)&bf[4] = *(const float4*)&b_s[p][k][64 + tx * 4];
            #pragma unroll
            for (int i = 0; i < TM; i++)
                #pragma unroll
                for (int j = 0; j < TN; j++)
                    acc[i][j] = fmaf(af[i], bf[j], acc[i][j]);
        }

        // store prefetched tile into the other buffer
        if (t + 1 < NT) {
            const int q = 1 - p;
            a_s[q][lkq + 0][lrow] = xa.x;
            a_s[q][lkq + 1][lrow] = xa.y;
            a_s[q][lkq + 2][lrow] = xa.z;
            a_s[q][lkq + 3][lrow] = xa.w;
            a_s[q][lkq + 0][lrow + 64] = xb.x;
            a_s[q][lkq + 1][lrow + 64] = xb.y;
            a_s[q][lkq + 2][lrow + 64] = xb.z;
            a_s[q][lkq + 3][lrow + 64] = xb.w;
            *(float4*)&b_s[q][ty][tx * 4]      = wga;
            *(float4*)&b_s[q][ty][64 + tx * 4] = wna;
            __syncthreads();
            p = q;
        }
    }

    // ---- epilogue: per-row noisy logits -> top-2 -> softmax -> scatter ----
    // row r = r0 + ty*8 + i is held by the 16 lanes sharing ty (a half-warp).
    #pragma unroll
    for (int i = 0; i < TM; i++) {
        const int r = r0 + ty * 8 + i;
        float4 nzv = *(const float4*)(nz + (size_t)r * EDIM + tx * 4);
        float v[4];
        const float nzf[4] = {nzv.x, nzv.y, nzv.z, nzv.w};
        #pragma unroll
        for (int jj = 0; jj < 4; jj++) {
            float g = acc[i][jj];
            float s = acc[i][jj + 4];
            // stable softplus: max(s,0) + log1p(exp(-|s|))
            float sp = fmaxf(s, 0.f) + log1pf(expf(-fabsf(s)));
            v[jj] = g + nzf[jj] * (sp + 0.01f);
        }

        // local top-2 (ascending expert index -> earlier index wins ties, like jax top_k)
        float v1 = -INFINITY, v2 = -INFINITY;
        int   i1 = 0x7fffffff, i2 = 0x7fffffff;
        #pragma unroll
        for (int jj = 0; jj < 4; jj++) {
            const int e = tx * 4 + jj;
            if (v[jj] > v1)      { v2 = v1; i2 = i1; v1 = v[jj]; i1 = e; }
            else if (v[jj] > v2) { v2 = v[jj]; i2 = e; }
        }

        // butterfly merge across the 16 lanes of the half-warp
        #pragma unroll
        for (int off = 1; off < 16; off <<= 1) {
            float ov1 = __shfl_xor_sync(0xffffffffu, v1, off);
            int   oi1 = __shfl_xor_sync(0xffffffffu, i1, off);
            float ov2 = __shfl_xor_sync(0xffffffffu, v2, off);
            int   oi2 = __shfl_xor_sync(0xffffffffu, i2, off);
            bool firstMine = (v1 > ov1) || (v1 == ov1 && i1 < oi1);
            float nv1, nv2; int ni1, ni2;
            if (firstMine) {
                nv1 = v1; ni1 = i1;
                bool s = (v2 > ov1) || (v2 == ov1 && i2 < oi1);
                nv2 = s ? v2 : ov1; ni2 = s ? i2 : oi1;
            } else {
                nv1 = ov1; ni1 = oi1;
                bool s = (ov2 > v1) || (ov2 == v1 && oi2 < i1);
                nv2 = s ? ov2 : v1; ni2 = s ? oi2 : i1;
            }
            v1 = nv1; i1 = ni1; v2 = nv2; i2 = ni2;
        }

        // softmax over [v1, v2] (max-shifted, matches jax.nn.softmax)
        float e2 = expf(v2 - v1);
        float denom = 1.f + e2;
        float g1 = 1.f / denom;
        float g2 = e2 / denom;

        float o[4];
        #pragma unroll
        for (int jj = 0; jj < 4; jj++) {
            const int e = tx * 4 + jj;
            o[jj] = (e == i1) ? g1 : ((e == i2) ? g2 : 0.f);
        }
        *(float4*)(out + (size_t)r * EDIM + tx * 4) = *(float4*)o;
    }
}

extern "C" void kernel_launch(void* const* d_in, const int* in_sizes, int n_in,
                              void* d_out, int out_size)
{
    const float* x  = (const float*)d_in[0];   // [32768, 2048]
    const float* wg = (const float*)d_in[1];   // [2048, 64]
    const float* wn = (const float*)d_in[2];   // [2048, 64]
    const float* nz = (const float*)d_in[3];   // [32768, 64]
    float* out = (float*)d_out;                // [32768, 64]

    const int B = in_sizes[0] / KDIM;          // 32768
    routing_kernel<<<B / BM, 256>>>(x, wg, wn, nz, out);
}

// round 3
// speedup vs baseline: 1.0321x; 1.0321x over previous
#include <cuda_runtime.h>
#include <math.h>
#include <stdint.h>

// RoutingLayer via legacy mma.sync tf32 (portable PTX, no sm_103a-only features).
// out[B,64] = scatter(softmax(top2(x@w_gate + noise*(softplus(x@w_noise)+0.01))))
// B=32768, D=2048, E=64. One GEMM, N=128: cols 0..63 gate, 64..127 noise.
// 3xTF32 split: x=hi+lo, w=hi+lo; compute hi*hi + hi*lo + lo*hi.

#define KDIM 2048
#define EDIM 64
#define BM   128
#define BKC  32
#define NCHUNK (KDIM / BKC)   // 64
#define TPB  256

// smem layout (floats). A stored [m][k] pitch 36; B stored [k][n] pitch 136.
#define AP 36
#define BP 136
#define OFF_AH 0
#define OFF_AL (128 * AP)
#define OFF_BH (2 * 128 * AP)
#define OFF_BL (2 * 128 * AP + 32 * BP)
#define BUF_FLOATS (2 * 128 * AP + 2 * 32 * BP)   // 17920
#define SMEM_FLOATS (2 * BUF_FLOATS)              // 35840 -> 143360 B
#define CP 134                                    // C staging pitch (reuses same smem)

__device__ __forceinline__ uint32_t tf32r(float a) {
    uint32_t u;
    asm("cvt.rna.tf32.f32 %0, %1;" : "=r"(u) : "f"(a));
    return u;
}

__device__ __forceinline__ void mma8(float* c, const uint32_t* a, const uint32_t* b) {
    asm volatile(
        "mma.sync.aligned.m16n8k8.row.col.f32.tf32.tf32.f32 "
        "{%0,%1,%2,%3}, {%4,%5,%6,%7}, {%8,%9}, {%0,%1,%2,%3};"
        : "+f"(c[0]), "+f"(c[1]), "+f"(c[2]), "+f"(c[3])
        : "r"(a[0]), "r"(a[1]), "r"(a[2]), "r"(a[3]), "r"(b[0]), "r"(b[1]));
}

__global__ __launch_bounds__(TPB, 1)
void routing_mma(const float* __restrict__ x,
                 const float* __restrict__ wg,
                 const float* __restrict__ wn,
                 const float* __restrict__ nz,
                 float* __restrict__ out)
{
    extern __shared__ float sm[];
    const int tid = threadIdx.x;
    const int wid = tid >> 5;
    const int lane = tid & 31;
    const int gid = lane >> 2;   // 0..7
    const int tig = lane & 3;    // 0..3
    const int r0 = blockIdx.x * BM;

    // warp tile: 32(M) x 64(N); warps arranged 4(M) x 2(N)
    const int mw = (wid >> 1) * 32;
    const int nwv = (wid & 1) * 64;

    float c[2][8][4];
    #pragma unroll
    for (int mt = 0; mt < 2; mt++)
        #pragma unroll
        for (int nt = 0; nt < 8; nt++)
            #pragma unroll
            for (int j = 0; j < 4; j++) c[mt][nt][j] = 0.f;

    // global load mappings
    const int xrow = tid >> 1;           // 0..127
    const int xkb  = (tid & 1) * 16;     // 0 or 16
    const float* xp = x + (size_t)(r0 + xrow) * KDIM + xkb;

    const int wkk = tid >> 3;            // 0..31
    const int wnb = (tid & 7) * 16;      // 0..112
    const float* wsrc = (wnb < 64) ? (wg + wnb) : (wn + (wnb - 64));

    float4 xv[4], wv[4];

    // prologue: load + convert + store chunk 0 into buffer 0
    #pragma unroll
    for (int q = 0; q < 4; q++) {
        xv[q] = *(const float4*)(xp + 4 * q);
        wv[q] = *(const float4*)(wsrc + (size_t)wkk * EDIM + 4 * q);
    }
    {
        float* bf = sm;
        #pragma unroll
        for (int q = 0; q < 4; q++) {
            float4 v = xv[q];
            uint32_t h0 = tf32r(v.x), h1 = tf32r(v.y), h2 = tf32r(v.z), h3 = tf32r(v.w);
            float4 hi = make_float4(__uint_as_float(h0), __uint_as_float(h1),
                                    __uint_as_float(h2), __uint_as_float(h3));
            float4 lo = make_float4(
                __uint_as_float(tf32r(v.x - hi.x)), __uint_as_float(tf32r(v.y - hi.y)),
                __uint_as_float(tf32r(v.z - hi.z)), __uint_as_float(tf32r(v.w - hi.w)));
            *(float4*)(bf + OFF_AH + xrow * AP + xkb + 4 * q) = hi;
            *(float4*)(bf + OFF_AL + xrow * AP + xkb + 4 * q) = lo;

            float4 w4 = wv[q];
            uint32_t g0 = tf32r(w4.x), g1 = tf32r(w4.y), g2 = tf32r(w4.z), g3 = tf32r(w4.w);
            float4 whi = make_float4(__uint_as_float(g0), __uint_as_float(g1),
                                     __uint_as_float(g2), __uint_as_float(g3));
            float4 wlo = make_float4(
                __uint_as_float(tf32r(w4.x - whi.x)), __uint_as_float(tf32r(w4.y - whi.y)),
                __uint_as_float(tf32r(w4.z - whi.z)), __uint_as_float(tf32r(w4.w - whi.w)));
            *(float4*)(bf + OFF_BH + wkk * BP + wnb + 4 * q) = whi;
            *(float4*)(bf + OFF_BL + wkk * BP + wnb + 4 * q) = wlo;
        }
    }
    __syncthreads();

    int p = 0;
    for (int t = 0; t < NCHUNK; t++) {
        // prefetch next chunk into registers
        if (t + 1 < NCHUNK) {
            const int k0 = (t + 1) * BKC;
            #pragma unroll
            for (int q = 0; q < 4; q++) {
                xv[q] = *(const float4*)(xp + k0 + 4 * q);
                wv[q] = *(const float4*)(wsrc + (size_t)(k0 + wkk) * EDIM + 4 * q);
            }
        }

        // compute on buffer p
        {
            const float* bf = sm + p * BUF_FLOATS;
            const float* AH = bf + OFF_AH;
            const float* AL = bf + OFF_AL;
            const float* BH = bf + OFF_BH;
            const float* BL = bf + OFF_BL;
            #pragma unroll
            for (int s = 0; s < 4; s++) {
                const int k0 = s * 8;
                uint32_t ah[2][4], al[2][4], bh[8][2], bl[8][2];
                #pragma unroll
                for (int mt = 0; mt < 2; mt++) {
                    const int m0 = mw + mt * 16;
                    ah[mt][0] = __float_as_uint(AH[(m0 + gid) * AP + k0 + tig]);
                    ah[mt][1] = __float_as_uint(AH[(m0 + gid + 8) * AP + k0 + tig]);
                    ah[mt][2] = __float_as_uint(AH[(m0 + gid) * AP + k0 + tig + 4]);
                    ah[mt][3] = __float_as_uint(AH[(m0 + gid + 8) * AP + k0 + tig + 4]);
                    al[mt][0] = __float_as_uint(AL[(m0 + gid) * AP + k0 + tig]);
                    al[mt][1] = __float_as_uint(AL[(m0 + gid + 8) * AP + k0 + tig]);
                    al[mt][2] = __float_as_uint(AL[(m0 + gid) * AP + k0 + tig + 4]);
                    al[mt][3] = __float_as_uint(AL[(m0 + gid + 8) * AP + k0 + tig + 4]);
                }
                #pragma unroll
                for (int nt = 0; nt < 8; nt++) {
                    const int n0 = nwv + nt * 8;
                    bh[nt][0] = __float_as_uint(BH[(k0 + tig) * BP + n0 + gid]);
                    bh[nt][1] = __float_as_uint(BH[(k0 + tig + 4) * BP + n0 + gid]);
                    bl[nt][0] = __float_as_uint(BL[(k0 + tig) * BP + n0 + gid]);
                    bl[nt][1] = __float_as_uint(BL[(k0 + tig + 4) * BP + n0 + gid]);
                }
                #pragma unroll
                for (int mt = 0; mt < 2; mt++)
                    #pragma unroll
                    for (int nt = 0; nt < 8; nt++)
                        mma8(c[mt][nt], ah[mt], bh[nt]);
                #pragma unroll
                for (int mt = 0; mt < 2; mt++)
                    #pragma unroll
                    for (int nt = 0; nt < 8; nt++)
                        mma8(c[mt][nt], ah[mt], bl[nt]);
                #pragma unroll
                for (int mt = 0; mt < 2; mt++)
                    #pragma unroll
                    for (int nt = 0; nt < 8; nt++)
                        mma8(c[mt][nt], al[mt], bh[nt]);
            }
        }

        // store prefetched chunk into the other buffer
        if (t + 1 < NCHUNK) {
            const int q2 = 1 - p;
            float* bf = sm + q2 * BUF_FLOATS;
            #pragma unroll
            for (int q = 0; q < 4; q++) {
                float4 v = xv[q];
                uint32_t h0 = tf32r(v.x), h1 = tf32r(v.y), h2 = tf32r(v.z), h3 = tf32r(v.w);
                float4 hi = make_float4(__uint_as_float(h0), __uint_as_float(h1),
                                        __uint_as_float(h2), __uint_as_float(h3));
                float4 lo = make_float4(
                    __uint_as_float(tf32r(v.x - hi.x)), __uint_as_float(tf32r(v.y - hi.y)),
                    __uint_as_float(tf32r(v.z - hi.z)), __uint_as_float(tf32r(v.w - hi.w)));
                *(float4*)(bf + OFF_AH + xrow * AP + xkb + 4 * q) = hi;
                *(float4*)(bf + OFF_AL + xrow * AP + xkb + 4 * q) = lo;

                float4 w4 = wv[q];
                uint32_t g0 = tf32r(w4.x), g1 = tf32r(w4.y), g2 = tf32r(w4.z), g3 = tf32r(w4.w);
                float4 whi = make_float4(__uint_as_float(g0), __uint_as_float(g1),
                                         __uint_as_float(g2), __uint_as_float(g3));
                float4 wlo = make_float4(
                    __uint_as_float(tf32r(w4.x - whi.x)), __uint_as_float(tf32r(w4.y - whi.y)),
                    __uint_as_float(tf32r(w4.z - whi.z)), __uint_as_float(tf32r(w4.w - whi.w)));
                *(float4*)(bf + OFF_BH + wkk * BP + wnb + 4 * q) = whi;
                *(float4*)(bf + OFF_BL + wkk * BP + wnb + 4 * q) = wlo;
            }
            __syncthreads();
            p = q2;
        }
    }

    // ---- stage C through smem (gate & noise cols live in different warps) ----
    __syncthreads();   // everyone done reading the last buffer
    {
        float* Cs = sm;
        #pragma unroll
        for (int mt = 0; mt < 2; mt++) {
            #pragma unroll
            for (int nt = 0; nt < 8; nt++) {
                const int m = mw + mt * 16 + gid;
                const int n = nwv + nt * 8 + 2 * tig;
                *(float2*)(Cs + m * CP + n) = make_float2(c[mt][nt][0], c[mt][nt][1]);
                *(float2*)(Cs + (m + 8) * CP + n) = make_float2(c[mt][nt][2], c[mt][nt][3]);
            }
        }
    }
    __syncthreads();

    // ---- epilogue: one thread per row ----
    if (tid < BM) {
        const int r = tid;
        const int row = r0 + r;
        const float* Cs = sm;
        const float4* nzr = (const float4*)(nz + (size_t)row * EDIM);

        float v1 = -INFINITY, v2 = -INFINITY;
        int i1 = 0x7fffffff, i2 = 0x7fffffff;
        #pragma unroll 4
        for (int e4 = 0; e4 < 16; e4++) {
            float4 z = nzr[e4];
            const float zf[4] = {z.x, z.y, z.z, z.w};
            #pragma unroll
            for (int j = 0; j < 4; j++) {
                const int e = e4 * 4 + j;
                float g = Cs[r * CP + e];
                float s = Cs[r * CP + 64 + e];
                float sp = fmaxf(s, 0.f) + log1pf(expf(-fabsf(s)));
                float v = fmaf(zf[j], sp + 0.01f, g);
                if (v > v1)      { v2 = v1; i2 = i1; v1 = v; i1 = e; }
                else if (v > v2) { v2 = v; i2 = e; }
            }
        }

        float e2 = expf(v2 - v1);
        float denom = 1.f + e2;
        float g1 = 1.f / denom;
        float g2 = e2 / denom;

        float4* orow = (float4*)(out + (size_t)row * EDIM);
        #pragma unroll 4
        for (int e4 = 0; e4 < 16; e4++) {
            float o[4];
            #pragma unroll
            for (int j = 0; j < 4; j++) {
                const int e = e4 * 4 + j;
                o[j] = (e == i1) ? g1 : ((e == i2) ? g2 : 0.f);
            }
            orow[e4] = make_float4(o[0], o[1], o[2], o[3]);
        }
    }
}

extern "C" void kernel_launch(void* const* d_in, const int* in_sizes, int n_in,
                              void* d_out, int out_size)
{
    const float* x  = (const float*)d_in[0];   // [32768, 2048]
    const float* wg = (const float*)d_in[1];   // [2048, 64]
    const float* wn = (const float*)d_in[2];   // [2048, 64]
    const float* nz = (const float*)d_in[3];   // [32768, 64]
    float* out = (float*)d_out;                // [32768, 64]

    cudaFuncSetAttribute(routing_mma, cudaFuncAttributeMaxDynamicSharedMemorySize,
                         SMEM_FLOATS * (int)sizeof(float));
    const int B = in_sizes[0] / KDIM;          // 32768
    routing_mma<<<B / BM, TPB, SMEM_FLOATS * sizeof(float)>>>(x, wg, wn, nz, out);
}

// round 4
// speedup vs baseline: 1.0631x; 1.0300x over previous
#include <cuda_runtime.h>
#include <math.h>
#include <stdint.h>

// RoutingLayer via legacy mma.sync tf32 (portable PTX for sm_103 target).
// out[B,64] = scatter(softmax(top2(x@w_gate + noise*(softplus(x@w_noise)+0.01))))
// B=32768, D=2048, E=64. Fused GEMM N=128 (0..63 gate, 64..127 noise).
// 3xTF32 split: hi*hi + hi*lo + lo*hi.  One flip of top-2 fails 1e-3 -> keep full split.

#define KDIM 2048
#define EDIM 64
#define BM   128
#define BKC  16
#define NCHUNK (KDIM / BKC)   // 128
#define TPB  256

// smem (float4 units): 2 buffers of [A: 2s*128row*4 | B: 2s*128n*4] = 1024+1024 f4 = 32KB
#define A_F4 1024
#define B_F4 1024
#define BUF_F4 2048
#define SMEM_BYTES (2 * BUF_F4 * 16)   // 65536

// pre-split weights, consumer-layout: [chunk][s][n][tig^ (n&3)] float4 = (bh_t, bh_t4, bl_t, bl_t4)
__device__ float4 g_wb[NCHUNK * B_F4];   // 2 MB

__device__ __forceinline__ float tf32f(float a) {
    uint32_t u;
    asm("cvt.rna.tf32.f32 %0, %1;" : "=r"(u) : "f"(a));
    return __uint_as_float(u);
}

__device__ __forceinline__ void mma8(float* c, uint32_t a0, uint32_t a1,
                                     uint32_t a2, uint32_t a3,
                                     uint32_t b0, uint32_t b1) {
    asm volatile(
        "mma.sync.aligned.m16n8k8.row.col.f32.tf32.tf32.f32 "
        "{%0,%1,%2,%3}, {%4,%5,%6,%7}, {%8,%9}, {%0,%1,%2,%3};"
        : "+f"(c[0]), "+f"(c[1]), "+f"(c[2]), "+f"(c[3])
        : "r"(a0), "r"(a1), "r"(a2), "r"(a3), "r"(b0), "r"(b1));
}

__device__ __forceinline__ uint32_t smem_u32(const void* p) {
    uint32_t a;
    asm("{ .reg .u64 t; cvta.to.shared.u64 t, %1; cvt.u32.u64 %0, t; }" : "=r"(a) : "l"(p));
    return a;
}
#define CP_ASYNC16(dst, src) \
    asm volatile("cp.async.cg.shared.global [%0], [%1], 16;" :: "r"(dst), "l"(src) : "memory")
#define CP_COMMIT() asm volatile("cp.async.commit_group;" ::: "memory")
#define CP_WAIT0()  asm volatile("cp.async.wait_group 0;" ::: "memory")

// ---- prep: split w into tf32 hi/lo, fragment-native layout ----
__global__ void prep_w(const float* __restrict__ wg, const float* __restrict__ wn) {
    int idx = blockIdx.x * blockDim.x + threadIdx.x;   // 0..262143
    int k = idx >> 7, n = idx & 127;
    float v = (n < 64) ? wg[k * 64 + n] : wn[k * 64 + (n - 64)];
    float hi = tf32f(v);
    float lo = tf32f(v - hi);
    int chunk = k >> 4, s = (k >> 3) & 1, tig = k & 3, pos = (k >> 2) & 1;
    int tigx = tig ^ (n & 3);
    int f4i = ((chunk * 2 + s) * 128 + n) * 4 + tigx;
    float* wbf = (float*)g_wb;
    wbf[f4i * 4 + pos]     = hi;
    wbf[f4i * 4 + pos + 2] = lo;
}

// ---- main ----
__global__ __launch_bounds__(TPB, 2)
void routing_mma(const float* __restrict__ x,
                 const float* __restrict__ nz,
                 float* __restrict__ out)
{
    extern __shared__ float4 sm4[];
    const int tid = threadIdx.x;
    const int wid = tid >> 5;
    const int lane = tid & 31;
    const int gid = lane >> 2;
    const int tig = lane & 3;
    const int txr = tig ^ (gid & 3);
    const int r0 = blockIdx.x * BM;
    const int m0 = wid * 16;              // warp rows [m0, m0+16)

    float c[16][4];
    #pragma unroll
    for (int nt = 0; nt < 16; nt++)
        #pragma unroll
        for (int j = 0; j < 4; j++) c[nt][j] = 0.f;

    // producer mappings
    const int arow = tid & 127;
    const int as   = tid >> 7;            // s-half 0/1
    const float* xp = x + (size_t)(r0 + arow) * KDIM + as * 8;
    float4* aDstBase0 = sm4 + as * 512 + arow * 4;   // + buf*2048
    const int arx = arow & 3;

    const uint32_t sb = smem_u32(sm4);

    // ---- prologue: chunk 0 into buffer 0 ----
    {
        float4 xa = *(const float4*)(xp);
        float4 xb = *(const float4*)(xp + 4);
        float v[8] = {xa.x, xa.y, xa.z, xa.w, xb.x, xb.y, xb.z, xb.w};
        float h[8], l[8];
        #pragma unroll
        for (int k = 0; k < 8; k++) { h[k] = tf32f(v[k]); l[k] = tf32f(v[k] - h[k]); }
        #pragma unroll
        for (int tg = 0; tg < 4; tg++)
            aDstBase0[tg ^ arx] = make_float4(h[tg], h[tg + 4], l[tg], l[tg + 4]);

        const float4* src = g_wb + tid;   // chunk 0
        #pragma unroll
        for (int j = 0; j < 4; j++) {
            uint32_t dst = sb + (uint32_t)(1024 + j * 256 + tid) * 16u;
            CP_ASYNC16(dst, src + j * 256);
        }
        CP_COMMIT();
        CP_WAIT0();
    }
    __syncthreads();

    int p = 0;
    for (int t = 0; t < NCHUNK; t++) {
        float4 xa, xb;
        const bool more = (t + 1 < NCHUNK);
        if (more) {
            xa = *(const float4*)(xp + (t + 1) * BKC);
            xb = *(const float4*)(xp + (t + 1) * BKC + 4);
            const float4* src = g_wb + (size_t)(t + 1) * 1024 + tid;
            const int q = 1 - p;
            #pragma unroll
            for (int j = 0; j < 4; j++) {
                uint32_t dst = sb + (uint32_t)(q * 2048 + 1024 + j * 256 + tid) * 16u;
                CP_ASYNC16(dst, src + j * 256);
            }
            CP_COMMIT();
        }

        // ---- compute chunk t from buffer p ----
        {
            const float4* buf = sm4 + p * 2048;
            #pragma unroll
            for (int s = 0; s < 2; s++) {
                float4 aL = buf[s * 512 + (m0 + gid) * 4 + txr];       // rows m0+gid
                float4 aH = buf[s * 512 + (m0 + gid + 8) * 4 + txr];   // rows m0+gid+8
                uint32_t ah0 = __float_as_uint(aL.x), ah1 = __float_as_uint(aH.x);
                uint32_t ah2 = __float_as_uint(aL.y), ah3 = __float_as_uint(aH.y);
                uint32_t al0 = __float_as_uint(aL.z), al1 = __float_as_uint(aH.z);
                uint32_t al2 = __float_as_uint(aL.w), al3 = __float_as_uint(aH.w);
                const float4* bbase = buf + 1024 + s * 512;
                #pragma unroll
                for (int nt = 0; nt < 16; nt++) {
                    float4 b4 = bbase[(nt * 8 + gid) * 4 + txr];
                    uint32_t bh0 = __float_as_uint(b4.x), bh1 = __float_as_uint(b4.y);
                    uint32_t bl0 = __float_as_uint(b4.z), bl1 = __float_as_uint(b4.w);
                    mma8(c[nt], ah0, ah1, ah2, ah3, bh0, bh1);   // hi*hi
                    mma8(c[nt], ah0, ah1, ah2, ah3, bl0, bl1);   // hi*lo
                    mma8(c[nt], al0, al1, al2, al3, bh0, bh1);   // lo*hi
                }
            }
        }

        if (more) {
            // A convert+store for t+1 into buffer q
            const int q = 1 - p;
            float v[8] = {xa.x, xa.y, xa.z, xa.w, xb.x, xb.y, xb.z, xb.w};
            float h[8], l[8];
            #pragma unroll
            for (int k = 0; k < 8; k++) { h[k] = tf32f(v[k]); l[k] = tf32f(v[k] - h[k]); }
            float4* aDst = aDstBase0 + q * 2048;
            #pragma unroll
            for (int tg = 0; tg < 4; tg++)
                aDst[tg ^ arx] = make_float4(h[tg], h[tg + 4], l[tg], l[tg + 4]);
            CP_WAIT0();
            __syncthreads();
            p = q;
        }
    }

    // ---- epilogue: rows rA = r0+m0+gid, rB = rA+8; intra-quad top-2 ----
    const int rA = r0 + m0 + gid;
    const int rB = rA + 8;
    float v1[2] = {-INFINITY, -INFINITY}, v2[2] = {-INFINITY, -INFINITY};
    int   i1[2] = {0x7fffffff, 0x7fffffff}, i2[2] = {0x7fffffff, 0x7fffffff};

    #pragma unroll
    for (int nt = 0; nt < 8; nt++) {
        const int e0 = nt * 8 + 2 * tig;
        float2 za = *(const float2*)(nz + (size_t)rA * EDIM + e0);
        float2 zb = *(const float2*)(nz + (size_t)rB * EDIM + e0);
        const float zz[2][2] = {{za.x, za.y}, {zb.x, zb.y}};
        #pragma unroll
        for (int hh = 0; hh < 2; hh++) {
            #pragma unroll
            for (int j = 0; j < 2; j++) {
                float g = c[nt][hh * 2 + j];
                float s = c[nt + 8][hh * 2 + j];
                float sp = fmaxf(s, 0.f) + log1pf(expf(-fabsf(s)));
                float v = fmaf(zz[hh][j], sp + 0.01f, g);
                const int e = e0 + j;
                if (v > v1[hh])      { v2[hh] = v1[hh]; i2[hh] = i1[hh]; v1[hh] = v; i1[hh] = e; }
                else if (v > v2[hh]) { v2[hh] = v; i2[hh] = e; }
            }
        }
    }

    #pragma unroll
    for (int hh = 0; hh < 2; hh++) {
        #pragma unroll
        for (int off = 1; off < 4; off <<= 1) {
            float ov1 = __shfl_xor_sync(0xffffffffu, v1[hh], off);
            int   oi1 = __shfl_xor_sync(0xffffffffu, i1[hh], off);
            float ov2 = __shfl_xor_sync(0xffffffffu, v2[hh], off);
            int   oi2 = __shfl_xor_sync(0xffffffffu, i2[hh], off);
            bool firstMine = (v1[hh] > ov1) || (v1[hh] == ov1 && i1[hh] < oi1);
            float nv1, nv2; int ni1, ni2;
            if (firstMine) {
                nv1 = v1[hh]; ni1 = i1[hh];
                bool s2 = (v2[hh] > ov1) || (v2[hh] == ov1 && i2[hh] < oi1);
                nv2 = s2 ? v2[hh] : ov1; ni2 = s2 ? i2[hh] : oi1;
            } else {
                nv1 = ov1; ni1 = oi1;
                bool s2 = (ov2 > v1[hh]) || (ov2 == v1[hh] && oi2 < i1[hh]);
                nv2 = s2 ? ov2 : v1[hh]; ni2 = s2 ? oi2 : i1[hh];
            }
            v1[hh] = nv1; i1[hh] = ni1; v2[hh] = nv2; i2[hh] = ni2;
        }
    }

    #pragma unroll
    for (int hh = 0; hh < 2; hh++) {
        float e2 = expf(v2[hh] - v1[hh]);
        float denom = 1.f + e2;
        float g1 = 1.f / denom;
        float g2 = e2 / denom;
        const int row = hh ? rB : rA;
        #pragma unroll
        for (int nt = 0; nt < 8; nt++) {
            const int e0 = nt * 8 + 2 * tig;
            float2 o;
            o.x = (e0 == i1[hh]) ? g1 : ((e0 == i2[hh]) ? g2 : 0.f);
            o.y = (e0 + 1 == i1[hh]) ? g1 : ((e0 + 1 == i2[hh]) ? g2 : 0.f);
            *(float2*)(out + (size_t)row * EDIM + e0) = o;
        }
    }
}

extern "C" void kernel_launch(void* const* d_in, const int* in_sizes, int n_in,
                              void* d_out, int out_size)
{
    const float* x  = (const float*)d_in[0];   // [32768, 2048]
    const float* wg = (const float*)d_in[1];   // [2048, 64]
    const float* wn = (const float*)d_in[2];   // [2048, 64]
    const float* nz = (const float*)d_in[3];   // [32768, 64]
    float* out = (float*)d_out;                // [32768, 64]

    prep_w<<<1024, 256>>>(wg, wn);

    cudaFuncSetAttribute(routing_mma, cudaFuncAttributeMaxDynamicSharedMemorySize,
                         SMEM_BYTES);
    const int B = in_sizes[0] / KDIM;          // 32768
    routing_mma<<<B / BM, TPB, SMEM_BYTES>>>(x, nz, out);
}

// round 5
// speedup vs baseline: 1.8148x; 1.7070x over previous
#include <cuda_runtime.h>
#include <cuda_fp16.h>
#include <math.h>
#include <stdint.h>

// RoutingLayer via mma.sync m16n8k16 fp16 (portable PTX for sm_103 target).
// out[B,64] = scatter(softmax(top2(x@w_gate + noise*(softplus(x@w_noise)+0.01))))
// B=32768, D=2048, E=64. Fused GEMM N=128 (0..63 gate, 64..127 noise).
// FP16x2 split: x=h0+h1, (256*w)=h0+h1; compute h0h0 + h0h1 + h1h0, scale by 2^-8.
// Dropped terms ~|xw|*2^-22: below fp32 accumulation noise.

#define KDIM 2048
#define EDIM 64
#define BM   128
#define BKC  32
#define NCHUNK (KDIM / BKC)   // 64
#define TPB  256

// smem layout in 16B units per buffer:
//   A: units [0, 1280): addr = (s*128 + row)*5 + tig   (row pitch 5 units = 80B)
//   B: units [1280, 2304): addr = 1280 + (s*128 + n)*4 + tig
#define BUF_U 2304
#define SMEM_BYTES (2 * BUF_U * 16)   // 73728

// pre-split weights: [k16 step s(128)][n(128)][tig(4)] uint4 = (b0_h0,b1_h0,b0_h1,b1_h1)
__device__ uint4 g_wb[128 * 128 * 4];   // 1 MB

__device__ __forceinline__ uint32_t pack2(__half lo, __half hi) {
    __half2 h = __halves2half2(lo, hi);
    return *(uint32_t*)&h;
}

__device__ __forceinline__ void mma16(float* c, uint32_t a0, uint32_t a1,
                                      uint32_t a2, uint32_t a3,
                                      uint32_t b0, uint32_t b1) {
    asm volatile(
        "mma.sync.aligned.m16n8k16.row.col.f32.f16.f16.f32 "
        "{%0,%1,%2,%3}, {%4,%5,%6,%7}, {%8,%9}, {%0,%1,%2,%3};"
        : "+f"(c[0]), "+f"(c[1]), "+f"(c[2]), "+f"(c[3])
        : "r"(a0), "r"(a1), "r"(a2), "r"(a3), "r"(b0), "r"(b1));
}

__device__ __forceinline__ uint32_t smem_u32(const void* p) {
    uint32_t a;
    asm("{ .reg .u64 t; cvta.to.shared.u64 t, %1; cvt.u32.u64 %0, t; }" : "=r"(a) : "l"(p));
    return a;
}
#define CP_ASYNC16(dst, src) \
    asm volatile("cp.async.cg.shared.global [%0], [%1], 16;" :: "r"(dst), "l"(src) : "memory")
#define CP_COMMIT() asm volatile("cp.async.commit_group;" ::: "memory")
#define CP_WAIT0()  asm volatile("cp.async.wait_group 0;" ::: "memory")

// ---- prep: split 256*w into fp16 (h0,h1), fragment-native B layout ----
__global__ void prep_w(const float* __restrict__ wg, const float* __restrict__ wn) {
    const int idx = blockIdx.x * blockDim.x + threadIdx.x;  // 0..65535
    const int tig = idx & 3;
    const int n   = (idx >> 2) & 127;
    const int s   = idx >> 9;            // k16 step 0..127
    const int kb  = s * 16;
    const int kk[4] = {kb + 2*tig, kb + 2*tig + 1, kb + 2*tig + 8, kb + 2*tig + 9};
    float v[4];
    #pragma unroll
    for (int j = 0; j < 4; j++)
        v[j] = 256.0f * ((n < 64) ? wg[kk[j] * 64 + n] : wn[kk[j] * 64 + (n - 64)]);
    __half h0[4], h1[4];
    #pragma unroll
    for (int j = 0; j < 4; j++) {
        h0[j] = __float2half_rn(v[j]);
        h1[j] = __float2half_rn(v[j] - __half2float(h0[j]));
    }
    uint4 w4;
    w4.x = pack2(h0[0], h0[1]);   // b0 (kpair tig), h0
    w4.y = pack2(h0[2], h0[3]);   // b1 (kpair tig+4), h0
    w4.z = pack2(h1[0], h1[1]);   // b0, h1
    w4.w = pack2(h1[2], h1[3]);   // b1, h1
    g_wb[(size_t)(s * 128 + n) * 4 + tig] = w4;
}

// ---- main ----
__global__ __launch_bounds__(TPB, 2)
void routing_mma(const float* __restrict__ x,
                 const float* __restrict__ nz,
                 float* __restrict__ out)
{
    extern __shared__ uint4 sm4[];
    const int tid = threadIdx.x;
    const int wid = tid >> 5;
    const int lane = tid & 31;
    const int gid = lane >> 2;
    const int tig = lane & 3;
    const int r0 = blockIdx.x * BM;
    const int m0 = wid * 16;              // warp rows [m0, m0+16)

    float c[16][4];
    #pragma unroll
    for (int nt = 0; nt < 16; nt++)
        #pragma unroll
        for (int j = 0; j < 4; j++) c[nt][j] = 0.f;

    // producer mappings: thread covers row (tid&127), k16-half (tid>>7) of each chunk
    const int arow = tid & 127;
    const int as   = tid >> 7;
    const float* xp = x + (size_t)(r0 + arow) * KDIM + as * 16;
    const int aunit0 = (as * 128 + arow) * 5;         // + tig, + buf*BUF_U

    const uint32_t sb = smem_u32(sm4);

    // ---- prologue: chunk 0 into buffer 0 ----
    {
        float v[16];
        #pragma unroll
        for (int q = 0; q < 4; q++)
            *(float4*)&v[4 * q] = *(const float4*)(xp + 4 * q);
        #pragma unroll
        for (int tg = 0; tg < 4; tg++) {
            const int i0 = 2*tg, i1 = 2*tg+1, i2 = 2*tg+8, i3 = 2*tg+9;
            __half a0 = __float2half_rn(v[i0]), a1 = __float2half_rn(v[i1]);
            __half a2 = __float2half_rn(v[i2]), a3 = __float2half_rn(v[i3]);
            uint4 w4;
            w4.x = pack2(a0, a1);
            w4.y = pack2(a2, a3);
            w4.z = pack2(__float2half_rn(v[i0] - __half2float(a0)),
                         __float2half_rn(v[i1] - __half2float(a1)));
            w4.w = pack2(__float2half_rn(v[i2] - __half2float(a2)),
                         __float2half_rn(v[i3] - __half2float(a3)));
            sm4[aunit0 + tg] = w4;
        }
        const uint4* src = g_wb + tid;   // chunk 0 = k16 steps 0,1 -> units [0,1024)
        #pragma unroll
        for (int j = 0; j < 4; j++) {
            uint32_t dst = sb + (uint32_t)(1280 + j * 256 + tid) * 16u;
            CP_ASYNC16(dst, src + j * 256);
        }
        CP_COMMIT();
        CP_WAIT0();
    }
    __syncthreads();

    int p = 0;
    for (int t = 0; t < NCHUNK; t++) {
        float v[16];
        const bool more = (t + 1 < NCHUNK);
        if (more) {
            #pragma unroll
            for (int q = 0; q < 4; q++)
                *(float4*)&v[4 * q] = *(const float4*)(xp + (t + 1) * BKC + 4 * q);
            const uint4* src = g_wb + (size_t)(t + 1) * 1024 + tid;
            const int qb = 1 - p;
            #pragma unroll
            for (int j = 0; j < 4; j++) {
                uint32_t dst = sb + (uint32_t)(qb * BUF_U + 1280 + j * 256 + tid) * 16u;
                CP_ASYNC16(dst, src + j * 256);
            }
            CP_COMMIT();
        }

        // ---- compute chunk t from buffer p ----
        {
            const uint4* buf = sm4 + p * BUF_U;
            #pragma unroll
            for (int s = 0; s < 2; s++) {
                uint4 Ag  = buf[(s * 128 + m0 + gid) * 5 + tig];
                uint4 Ag8 = buf[(s * 128 + m0 + gid + 8) * 5 + tig];
                const uint4* bb = buf + 1280 + s * 512;
                #pragma unroll
                for (int nt = 0; nt < 16; nt++) {
                    uint4 Bv = bb[(nt * 8 + gid) * 4 + tig];
                    mma16(c[nt], Ag.x, Ag8.x, Ag.y, Ag8.y, Bv.x, Bv.y);  // h0a*h0b
                    mma16(c[nt], Ag.x, Ag8.x, Ag.y, Ag8.y, Bv.z, Bv.w);  // h0a*h1b
                    mma16(c[nt], Ag.z, Ag8.z, Ag.w, Ag8.w, Bv.x, Bv.y);  // h1a*h0b
                }
            }
        }

        if (more) {
            const int qb = 1 - p;
            #pragma unroll
            for (int tg = 0; tg < 4; tg++) {
                const int i0 = 2*tg, i1 = 2*tg+1, i2 = 2*tg+8, i3 = 2*tg+9;
                __half a0 = __float2half_rn(v[i0]), a1 = __float2half_rn(v[i1]);
                __half a2 = __float2half_rn(v[i2]), a3 = __float2half_rn(v[i3]);
                uint4 w4;
                w4.x = pack2(a0, a1);
                w4.y = pack2(a2, a3);
                w4.z = pack2(__float2half_rn(v[i0] - __half2float(a0)),
                             __float2half_rn(v[i1] - __half2float(a1)));
                w4.w = pack2(__float2half_rn(v[i2] - __half2float(a2)),
                             __float2half_rn(v[i3] - __half2float(a3)));
                sm4[qb * BUF_U + aunit0 + tg] = w4;
            }
            CP_WAIT0();
            __syncthreads();
            p = qb;
        }
    }

    // ---- epilogue: rows rA = r0+m0+gid, rB = rA+8; intra-quad top-2 ----
    const float S = 1.0f / 256.0f;   // undo weight pre-scale (exact)
    const int rA = r0 + m0 + gid;
    const int rB = rA + 8;
    float v1[2] = {-INFINITY, -INFINITY}, v2[2] = {-INFINITY, -INFINITY};
    int   i1[2] = {0x7fffffff, 0x7fffffff}, i2[2] = {0x7fffffff, 0x7fffffff};

    #pragma unroll
    for (int nt = 0; nt < 8; nt++) {
        const int e0 = nt * 8 + 2 * tig;
        float2 za = *(const float2*)(nz + (size_t)rA * EDIM + e0);
        float2 zb = *(const float2*)(nz + (size_t)rB * EDIM + e0);
        const float zz[2][2] = {{za.x, za.y}, {zb.x, zb.y}};
        #pragma unroll
        for (int hh = 0; hh < 2; hh++) {
            #pragma unroll
            for (int j = 0; j < 2; j++) {
                float g = c[nt][hh * 2 + j] * S;
                float s = c[nt + 8][hh * 2 + j] * S;
                float sp = fmaxf(s, 0.f) + log1pf(expf(-fabsf(s)));
                float v = fmaf(zz[hh][j], sp + 0.01f, g);
                const int e = e0 + j;
                if (v > v1[hh])      { v2[hh] = v1[hh]; i2[hh] = i1[hh]; v1[hh] = v; i1[hh] = e; }
                else if (v > v2[hh]) { v2[hh] = v; i2[hh] = e; }
            }
        }
    }

    #pragma unroll
    for (int hh = 0; hh < 2; hh++) {
        #pragma unroll
        for (int off = 1; off < 4; off <<= 1) {
            float ov1 = __shfl_xor_sync(0xffffffffu, v1[hh], off);
            int   oi1 = __shfl_xor_sync(0xffffffffu, i1[hh], off);
            float ov2 = __shfl_xor_sync(0xffffffffu, v2[hh], off);
            int   oi2 = __shfl_xor_sync(0xffffffffu, i2[hh], off);
            bool firstMine = (v1[hh] > ov1) || (v1[hh] == ov1 && i1[hh] < oi1);
            float nv1, nv2; int ni1, ni2;
            if (firstMine) {
                nv1 = v1[hh]; ni1 = i1[hh];
                bool s2 = (v2[hh] > ov1) || (v2[hh] == ov1 && i2[hh] < oi1);
                nv2 = s2 ? v2[hh] : ov1; ni2 = s2 ? i2[hh] : oi1;
            } else {
                nv1 = ov1; ni1 = oi1;
                bool s2 = (ov2 > v1[hh]) || (ov2 == v1[hh] && oi2 < i1[hh]);
                nv2 = s2 ? ov2 : v1[hh]; ni2 = s2 ? oi2 : i1[hh];
            }
            v1[hh] = nv1; i1[hh] = ni1; v2[hh] = nv2; i2[hh] = ni2;
        }
    }

    #pragma unroll
    for (int hh = 0; hh < 2; hh++) {
        float e2 = expf(v2[hh] - v1[hh]);
        float denom = 1.f + e2;
        float g1 = 1.f / denom;
        float g2 = e2 / denom;
        const int row = hh ? rB : rA;
        #pragma unroll
        for (int nt = 0; nt < 8; nt++) {
            const int e0 = nt * 8 + 2 * tig;
            float2 o;
            o.x = (e0 == i1[hh]) ? g1 : ((e0 == i2[hh]) ? g2 : 0.f);
            o.y = (e0 + 1 == i1[hh]) ? g1 : ((e0 + 1 == i2[hh]) ? g2 : 0.f);
            *(float2*)(out + (size_t)row * EDIM + e0) = o;
        }
    }
}

extern "C" void kernel_launch(void* const* d_in, const int* in_sizes, int n_in,
                              void* d_out, int out_size)
{
    const float* x  = (const float*)d_in[0];   // [32768, 2048]
    const float* wg = (const float*)d_in[1];   // [2048, 64]
    const float* wn = (const float*)d_in[2];   // [2048, 64]
    const float* nz = (const float*)d_in[3];   // [32768, 64]
    float* out = (float*)d_out;                // [32768, 64]

    prep_w<<<256, 256>>>(wg, wn);

    cudaFuncSetAttribute(routing_mma, cudaFuncAttributeMaxDynamicSharedMemorySize,
                         SMEM_BYTES);
    const int B = in_sizes[0] / KDIM;          // 32768
    routing_mma<<<B / BM, TPB, SMEM_BYTES>>>(x, nz, out);
}